// round 3
// baseline (speedup 1.0000x reference)
#include <cuda_runtime.h>
#include <math.h>

#define Bb 128
#define Tt 100
#define Dd 2048
#define Hh 1024
#define Oo 20
#define BH (Bb*Hh)          // 131072
#define TW 91               // T - WINDOW + 1

// ---------------- device scratch (static: no allocations allowed) ----------
__device__ float g_A[Bb*Tt*Hh];      // input projection G1 (no bias), [m=b*100+t][i]
__device__ float g_S[Tt*BH];         // spike history [t][b*H+h]
__device__ float g_G2[BH];           // recurrent GEMM result for current step
__device__ float g_hmem[BH];
__device__ float g_omem[Bb*Oo];
__device__ float g_osum[Bb*Oo];
__device__ float g_nbr[Tt];

// ---------------- init -------------------------------------------------------
__global__ void k_init(const float* __restrict__ hm, const float* __restrict__ om) {
    int idx = blockIdx.x * blockDim.x + threadIdx.x;
    if (idx < BH)                        g_hmem[idx] = hm[idx];
    else if (idx < BH + Bb*Oo)           g_omem[idx - BH] = om[idx - BH];
    else if (idx < BH + 2*Bb*Oo)         g_osum[idx - BH - Bb*Oo] = 0.f;
    else if (idx < BH + 2*Bb*Oo + Tt)    g_nbr[idx - BH - 2*Bb*Oo] = 0.f;
}

// ---------------- input GEMM: g_A = X @ Wi2h^T  -----------------------------
// Plain sequential ascending-k FMA, single accumulator per output element
// (matches cuBLAS SIMT sgemm / Eigen gebp reduction order).
// C[12800,1024], K=2048. BM=128, BN=64, BK=16, 256 threads, 8x4 per thread.
__global__ __launch_bounds__(256) void k_ingemm(
    const float* __restrict__ X, const float* __restrict__ W)
{
    __shared__ float As[2][16][132];
    __shared__ float Bs[2][16][68];
    const int m0 = blockIdx.y * 128;
    const int n0 = blockIdx.x * 64;
    const int tid = threadIdx.x;
    const int lr = tid >> 2;            // 0..63
    const int lc = (tid & 3) << 2;      // 0,4,8,12
    const int tm = tid & 15, tn = tid >> 4;

    float c[8][4];
#pragma unroll
    for (int i = 0; i < 8; i++)
#pragma unroll
        for (int j = 0; j < 4; j++) c[i][j] = 0.f;

    const float* pa0 = X + (size_t)(m0 + lr) * Dd + lc;
    const float* pa1 = X + (size_t)(m0 + lr + 64) * Dd + lc;
    const float* pb0 = W + (size_t)(n0 + lr) * Dd + lc;

    float4 ra0 = *(const float4*)(pa0);
    float4 ra1 = *(const float4*)(pa1);
    float4 rb0 = *(const float4*)(pb0);
#pragma unroll
    for (int j = 0; j < 4; j++) {
        As[0][lc + j][lr]      = ((const float*)&ra0)[j];
        As[0][lc + j][lr + 64] = ((const float*)&ra1)[j];
        Bs[0][lc + j][lr]      = ((const float*)&rb0)[j];
    }
    __syncthreads();

    const int NK = Dd / 16;
    int buf = 0;
    for (int kt = 0; kt < NK; ++kt) {
        if (kt + 1 < NK) {
            int ko = (kt + 1) * 16;
            ra0 = *(const float4*)(pa0 + ko);
            ra1 = *(const float4*)(pa1 + ko);
            rb0 = *(const float4*)(pb0 + ko);
        }
#pragma unroll
        for (int kk = 0; kk < 16; ++kk) {
            float4 a0 = *(const float4*)&As[buf][kk][tm * 4];
            float4 a1 = *(const float4*)&As[buf][kk][tm * 4 + 64];
            float4 b  = *(const float4*)&Bs[buf][kk][tn * 4];
            float av[8] = {a0.x,a0.y,a0.z,a0.w,a1.x,a1.y,a1.z,a1.w};
            float bv[4] = {b.x,b.y,b.z,b.w};
#pragma unroll
            for (int i = 0; i < 8; i++)
#pragma unroll
                for (int j = 0; j < 4; j++)
                    c[i][j] = fmaf(av[i], bv[j], c[i][j]);
        }
        if (kt + 1 < NK) {
            int nb = buf ^ 1;
#pragma unroll
            for (int j = 0; j < 4; j++) {
                As[nb][lc + j][lr]      = ((const float*)&ra0)[j];
                As[nb][lc + j][lr + 64] = ((const float*)&ra1)[j];
                Bs[nb][lc + j][lr]      = ((const float*)&rb0)[j];
            }
        }
        buf ^= 1;
        __syncthreads();
    }

#pragma unroll
    for (int i = 0; i < 8; i++) {
        int row = m0 + tm * 4 + (i & 3) + ((i >= 4) ? 64 : 0);
        float4 v;
        v.x = c[i][0]; v.y = c[i][1]; v.z = c[i][2]; v.w = c[i][3];
        *(float4*)&g_A[(size_t)row * Hh + n0 + tn * 4] = v;
    }
}

// ---------------- recurrent GEMM: g_G2 = hs_prev @ Wh2h^T -------------------
// NO split-K: full K=1024 sequential ascending per output element.
// BM=32, BN=32, BK=32, 256 threads, 2x2 per thread. grid = 32x4 = 128 blocks.
__global__ __launch_bounds__(256) void k_recur(
    const float* __restrict__ hs0, const float* __restrict__ W, int t)
{
    __shared__ float As[2][32][34];
    __shared__ float Bs[2][32][34];
    const int tid = threadIdx.x;
    const int m0 = blockIdx.y * 32;
    const int n0 = blockIdx.x * 32;
    const int lr = tid >> 3;            // 0..31
    const int lc = (tid & 7) << 2;      // 0,4,...,28
    const int txm = tid & 15, txn = tid >> 4;

    const float* Amat = (t == 0) ? hs0 : (g_S + (size_t)(t - 1) * BH);
    const float* pa = Amat + (size_t)(m0 + lr) * Hh + lc;
    const float* pb = W + (size_t)(n0 + lr) * Hh + lc;

    float a00 = 0.f, a01 = 0.f, a10 = 0.f, a11 = 0.f;

    float4 ra = *(const float4*)pa;
    float4 rb = *(const float4*)pb;
#pragma unroll
    for (int j = 0; j < 4; j++) {
        As[0][lc + j][lr] = ((const float*)&ra)[j];
        Bs[0][lc + j][lr] = ((const float*)&rb)[j];
    }
    __syncthreads();

    const int NK = Hh / 32;   // 32
    int buf = 0;
    for (int kt = 0; kt < NK; ++kt) {
        if (kt + 1 < NK) {
            ra = *(const float4*)(pa + (kt + 1) * 32);
            rb = *(const float4*)(pb + (kt + 1) * 32);
        }
#pragma unroll
        for (int kk = 0; kk < 32; ++kk) {
            float2 a = *(const float2*)&As[buf][kk][txm * 2];
            float2 b = *(const float2*)&Bs[buf][kk][txn * 2];
            a00 = fmaf(a.x, b.x, a00);
            a01 = fmaf(a.x, b.y, a01);
            a10 = fmaf(a.y, b.x, a10);
            a11 = fmaf(a.y, b.y, a11);
        }
        if (kt + 1 < NK) {
            int nb = buf ^ 1;
#pragma unroll
            for (int j = 0; j < 4; j++) {
                As[nb][lc + j][lr] = ((const float*)&ra)[j];
                Bs[nb][lc + j][lr] = ((const float*)&rb)[j];
            }
        }
        buf ^= 1;
        __syncthreads();
    }

    int m = m0 + txm * 2, n = n0 + txn * 2;
    g_G2[(size_t)m * Hh + n]           = a00;
    g_G2[(size_t)m * Hh + n + 1]       = a01;
    g_G2[(size_t)(m + 1) * Hh + n]     = a10;
    g_G2[(size_t)(m + 1) * Hh + n + 1] = a11;
}

// ---------------- hidden membrane update -----------------------------------
__global__ __launch_bounds__(256) void k_hidden(
    const float* __restrict__ b1, const float* __restrict__ b2,
    const float* __restrict__ thr_h, int t)
{
    int bh = blockIdx.x * 256 + threadIdx.x;
    int b = bh >> 10, i = bh & 1023;

    float G1 = g_A[((size_t)b * Tt + t) * Hh + i];
    float G2 = g_G2[bh];
    float v = ((G1 + b1[i]) + G2) + b2[i];   // reference's left-associativity
    float m = g_hmem[bh] + v;
    float th = thr_h[i];
    float sp = (m - th > 0.f) ? 1.f : 0.f;
    m = m * (1.f - sp);
    float neg = (m < -th) ? 1.f : 0.f;
    m = m * (1.f - neg) - th * neg;
    g_hmem[bh] = m;
    g_S[(size_t)t * BH + bh] = sp;

    __shared__ float red[256];
    red[threadIdx.x] = sp;
    __syncthreads();
    for (int s = 128; s > 0; s >>= 1) {
        if (threadIdx.x < s) red[threadIdx.x] += red[threadIdx.x + s];
        __syncthreads();
    }
    if (threadIdx.x == 0) atomicAdd(&g_nbr[t], red[0] * (1.f / Bb));
}

// ---------------- output layer: GEMM + membrane update ---------------------
__global__ __launch_bounds__(128) void k_out(const float* __restrict__ W2,
    const float* __restrict__ b2o, const float* __restrict__ thr_o, int t)
{
    __shared__ float rs[Oo][128];
    __shared__ float spsm[Oo];
    int b = blockIdx.x, tid = threadIdx.x;
    const float* hs = g_S + (size_t)t * BH + (size_t)b * Hh;
    float acc[Oo];
#pragma unroll
    for (int o = 0; o < Oo; o++) acc[o] = 0.f;
    for (int k = tid; k < Hh; k += 128) {
        float h = hs[k];
#pragma unroll
        for (int o = 0; o < Oo; o++) acc[o] = fmaf(h, W2[o * Hh + k], acc[o]);
    }
#pragma unroll
    for (int o = 0; o < Oo; o++) rs[o][tid] = acc[o];
    __syncthreads();
    for (int s = 64; s > 0; s >>= 1) {
        if (tid < s)
#pragma unroll
            for (int o = 0; o < Oo; o++) rs[o][tid] += rs[o][tid + s];
        __syncthreads();
    }
    if (tid < Oo) {
        int o = tid;
        float m = g_omem[b * Oo + o] + (rs[o][0] + b2o[o]);
        float th = thr_o[o];
        float sp = (m - th > 0.f) ? 1.f : 0.f;
        m = m * (1.f - sp);
        float neg = (m < -th) ? 1.f : 0.f;
        m = m * (1.f - neg) - th * neg;
        g_omem[b * Oo + o] = m;
        g_osum[b * Oo + o] += sp;
        spsm[o] = sp;
    }
    __syncthreads();
    if (tid == 0) {
        float s = 0.f;
        for (int o = 0; o < Oo; o++) s += spsm[o];
        atomicAdd(&g_nbr[t], s * (1.f / Bb));
    }
}

// ---------------- sliding-window filter ------------------------------------
__global__ __launch_bounds__(128) void k_filt(float* __restrict__ out) {
    __shared__ float sm[128 * TW];
    int bh = blockIdx.x * 128 + threadIdx.x;
    const float* S = g_S + bh;
    float s = 0.f;
#pragma unroll
    for (int tt = 0; tt < 10; ++tt) s += S[(size_t)tt * BH];
    sm[threadIdx.x * TW + 0] = s / 10.0f;
    for (int tt = 10; tt < Tt; ++tt) {
        s += S[(size_t)tt * BH] - S[(size_t)(tt - 10) * BH];
        sm[threadIdx.x * TW + (tt - 9)] = s / 10.0f;
    }
    __syncthreads();
    float* dst = out + 229 + (size_t)blockIdx.x * 128 * TW;
    for (int idx = threadIdx.x; idx < 128 * TW; idx += 128) dst[idx] = sm[idx];
}

// ---------------- predictions / loss / nbr_events --------------------------
__global__ void k_final(const int* __restrict__ labels, float* __restrict__ out) {
    int tid = threadIdx.x;  // 256 threads
    __shared__ float red[128];
    if (tid < 128) {
        int b = tid;
        float mx = g_osum[b * Oo];
        int arg = 0;
        for (int o = 1; o < Oo; o++) {
            float v = g_osum[b * Oo + o];
            if (v > mx) { mx = v; arg = o; }
        }
        float se = 0.f;
        for (int o = 0; o < Oo; o++) se += expf(g_osum[b * Oo + o] - mx);
        float lse = mx + logf(se);
        out[b] = (float)arg;
        int lab = labels[b];
        red[b] = -(g_osum[b * Oo + lab] - lse);
    }
    __syncthreads();
    for (int s = 64; s > 0; s >>= 1) {
        if (tid < s) red[tid] += red[tid + s];
        __syncthreads();
    }
    if (tid == 0) out[128] = red[0] / (float)Bb;
    if (tid >= 128 && tid < 128 + Tt) out[129 + (tid - 128)] = g_nbr[tid - 128];
}

// ---------------- launcher --------------------------------------------------
extern "C" void kernel_launch(void* const* d_in, const int* in_sizes, int n_in,
                              void* d_out, int out_size) {
    const float* input = (const float*)d_in[0];
    const int*   labels = (const int*)d_in[1];
    const float* hmem0 = (const float*)d_in[2];
    const float* hspk0 = (const float*)d_in[3];
    const float* omem0 = (const float*)d_in[4];
    const float* Wi2h  = (const float*)d_in[6];
    const float* bi2h  = (const float*)d_in[7];
    const float* Wh2h  = (const float*)d_in[8];
    const float* bh2h  = (const float*)d_in[9];
    const float* Wh2o  = (const float*)d_in[10];
    const float* bh2o  = (const float*)d_in[11];
    const float* thr_h = (const float*)d_in[12];
    const float* thr_o = (const float*)d_in[13];
    float* out = (float*)d_out;

    int initN = BH + 2 * Bb * Oo + Tt;
    k_init<<<(initN + 255) / 256, 256>>>(hmem0, omem0);
    k_ingemm<<<dim3(Hh / 64, (Bb * Tt) / 128), 256>>>(input, Wi2h);
    for (int t = 0; t < Tt; ++t) {
        k_recur<<<dim3(Hh / 32, Bb / 32), 256>>>(hspk0, Wh2h, t);
        k_hidden<<<BH / 256, 256>>>(bi2h, bh2h, thr_h, t);
        k_out<<<Bb, 128>>>(Wh2o, bh2o, thr_o, t);
    }
    k_filt<<<BH / 128, 128>>>(out);
    k_final<<<1, 256>>>(labels, out);
}